// round 12
// baseline (speedup 1.0000x reference)
#include <cuda_runtime.h>
#include <math.h>

typedef unsigned long long u64;

#define BATCH  512
#define TLEN   1024
#define HID    64
#define M_TOTAL (BATCH*TLEN)
#define CHUNKS 8
#define CT     (TLEN/CHUNKS)          // 128 steps per chunk

#define NBLK        592               // 4 blocks/SM x 148 SMs: all resident
#define NG          512               // gemm tasks per (l,c)  (1 batch row each)
#define NS          256               // scan tasks per (l,c)  (2 batch rows each)
#define TOTAL_TASKS (32*(NG+NS) + CHUNKS*NG)   // 28672

// Per-layer scratch.
__device__ __align__(16) float g_pre [4][M_TOTAL*HID];
__device__ __align__(16) float g_hout[4][M_TOTAL*HID];
__device__ __align__(16) float g_hst [4][BATCH*HID];    // h carry between chunks

// Dependency flags + dynamic task ticket.
__device__ int gflag [4][CHUNKS][BATCH];   // pre(l,c,row) ready
__device__ int sflag2[4][CHUNKS][NS];      // h(l,c, 2-row group) ready
__device__ unsigned g_task_ctr;

__device__ __forceinline__ int ld_acq(const int* p) {
    int v;
    asm volatile("ld.acquire.gpu.global.b32 %0, [%1];" : "=r"(v) : "l"(p) : "memory");
    return v;
}
__device__ __forceinline__ void st_rel(int* p, int v) {
    asm volatile("st.release.gpu.global.b32 [%0], %1;" :: "l"(p), "r"(v) : "memory");
}
__device__ __forceinline__ void bar_sync(int id) {
    asm volatile("bar.sync %0, 64;" :: "r"(id) : "memory");
}

__device__ __forceinline__ u64 pk2(float x, float y) {
    u64 r; asm("mov.b64 %0,{%1,%2};" : "=l"(r) : "f"(x), "f"(y)); return r;
}
__device__ __forceinline__ void upk2(u64 v, float &x, float &y) {
    asm("mov.b64 {%0,%1},%2;" : "=f"(x), "=f"(y) : "l"(v));
}
#define FMA2(d,a,b,c) asm("fma.rn.f32x2 %0,%1,%2,%3;" : "=l"(d) : "l"(a), "l"(b), "l"(c))
#define ADD2(d,a,b)   asm("add.rn.f32x2 %0,%1,%2;"    : "=l"(d) : "l"(a), "l"(b))

__device__ __forceinline__ float tanh_fast(float x) {
    float xc = fminf(fmaxf(x, -15.0f), 15.0f);
    float e;
    asm("ex2.approx.f32 %0, %1;" : "=f"(e) : "f"(xc * 2.885390081777927f));
    float r;
    asm("rcp.approx.f32 %0, %1;" : "=f"(r) : "f"(e + 1.0f));
    return (e - 1.0f) * r;
}

// Shared memory union: gemm staging vs scan h buffers.
struct SmemGemm {
    float Xs[128*64];   // 32 KB, un-duplicated X tile [m][k]
    u64   Wp[64*32];    // 16 KB, {W[2p][k],W[2p+1][k]} pairs [k][np]
};
struct SmemScan {
    float hbuf[2][2][64];   // [row][phase][col]
};
union SmemU {
    SmemGemm g;
    SmemScan s;
};

// ============================================================================
// GEMM tile body, L1-lean variant: 128 threads, 128 rows x 64 cols, 8x8/thread.
// X read as float4 (4 k per LDS.128, no duplication); {x,x} packing done in
// registers (ALU pipe). W as n-pair u64, 2x LDS.128 per k. Per 4-k group per
// thread: 8 X-LDS.128 + 8 W-LDS.128 + ~32 MOV + 128 FFMA2 -> FMA-bound.
// ============================================================================
__device__ __forceinline__ void gemm_body(
    SmemGemm& sm,
    const float* __restrict__ X, const float* __restrict__ W,
    const float* __restrict__ b1, const float* __restrict__ b2,
    float* __restrict__ Out, int K, long m0)
{
    float* Xs = sm.Xs;
    u64*   Wp = sm.Wp;

    const int tid = threadIdx.x;
    const int nt  = tid & 7;
    const int mt  = tid >> 3;
    const int np0 = nt * 4;
    const int mr  = mt * 8;

    // ---- stage X: 128 rows x 64 k (zero-pad k>=K), coalesced scalar loads
    #pragma unroll 8
    for (int i = 0; i < 64; i++) {
        int idx = i * 128 + tid;       // 0..8191
        int m  = idx >> 6;
        int k  = idx & 63;
        Xs[idx] = (k < K) ? X[(m0 + m) * (long)K + k] : 0.f;
    }
    // ---- stage W pairs: Wp[k][np'] = {W[2np][k], W[2np+1][k]}, swizzled
    #pragma unroll 4
    for (int i = 0; i < 16; i++) {
        int idx = i * 128 + tid;       // 0..2047
        int k  = idx >> 5;
        int np = idx & 31;
        float w0 = 0.f, w1 = 0.f;
        if (k < K) {
            w0 = W[(2*np)   * (long)K + k];
            w1 = W[(2*np+1) * (long)K + k];
        }
        Wp[k * 32 + (np ^ ((k & 7) << 2))] = pk2(w0, w1);
    }
    __syncthreads();

    u64 acc[8][4];
    {
        u64 bias[4];
        #pragma unroll
        for (int p = 0; p < 4; p++) {
            int n = (np0 + p) * 2;
            float v0 = b1[n], v1 = b1[n+1];
            if (b2) { v0 += b2[n]; v1 += b2[n+1]; }
            bias[p] = pk2(v0, v1);
        }
        #pragma unroll
        for (int i = 0; i < 8; i++)
            #pragma unroll
            for (int p = 0; p < 4; p++) acc[i][p] = bias[p];
    }

    const float4* Xs4 = reinterpret_cast<const float4*>(Xs);   // [m][16]

    #pragma unroll 4
    for (int k4 = 0; k4 < 16; k4++) {
        // W pairs for the 4 k's of this group (8x LDS.128)
        ulonglong2 wA[4], wB[4];
        #pragma unroll
        for (int kk = 0; kk < 4; kk++) {
            int k = 4*k4 + kk;
            int base = k * 32 + (np0 ^ ((k & 7) << 2));
            wA[kk] = *reinterpret_cast<const ulonglong2*>(&Wp[base]);
            wB[kk] = *reinterpret_cast<const ulonglong2*>(&Wp[base + 2]);
        }
        #pragma unroll
        for (int i = 0; i < 8; i++) {
            float4 xv = Xs4[(mr + i) * 16 + k4];   // 4 k-values, one LDS.128
            u64 xd;
            xd = pk2(xv.x, xv.x);
            FMA2(acc[i][0], xd, wA[0].x, acc[i][0]);
            FMA2(acc[i][1], xd, wA[0].y, acc[i][1]);
            FMA2(acc[i][2], xd, wB[0].x, acc[i][2]);
            FMA2(acc[i][3], xd, wB[0].y, acc[i][3]);
            xd = pk2(xv.y, xv.y);
            FMA2(acc[i][0], xd, wA[1].x, acc[i][0]);
            FMA2(acc[i][1], xd, wA[1].y, acc[i][1]);
            FMA2(acc[i][2], xd, wB[1].x, acc[i][2]);
            FMA2(acc[i][3], xd, wB[1].y, acc[i][3]);
            xd = pk2(xv.z, xv.z);
            FMA2(acc[i][0], xd, wA[2].x, acc[i][0]);
            FMA2(acc[i][1], xd, wA[2].y, acc[i][1]);
            FMA2(acc[i][2], xd, wB[2].x, acc[i][2]);
            FMA2(acc[i][3], xd, wB[2].y, acc[i][3]);
            xd = pk2(xv.w, xv.w);
            FMA2(acc[i][0], xd, wA[3].x, acc[i][0]);
            FMA2(acc[i][1], xd, wA[3].y, acc[i][1]);
            FMA2(acc[i][2], xd, wB[3].x, acc[i][2]);
            FMA2(acc[i][3], xd, wB[3].y, acc[i][3]);
        }
    }

    const int n0 = np0 * 2;
    #pragma unroll
    for (int i = 0; i < 8; i++) {
        float* dst = &Out[(m0 + mr + i) * 64 + n0];
        ulonglong2 v0, v1;
        v0.x = acc[i][0]; v0.y = acc[i][1];
        v1.x = acc[i][2]; v1.y = acc[i][3];
        *reinterpret_cast<ulonglong2*>(dst)     = v0;
        *reinterpret_cast<ulonglong2*>(dst + 4) = v1;
    }
}

__global__ void zero_flags()
{
    int idx = blockIdx.x * blockDim.x + threadIdx.x;
    const int NGf = 4 * CHUNKS * BATCH;
    const int NSf = 4 * CHUNKS * NS;
    if (idx < NGf) (&gflag [0][0][0])[idx] = 0;
    if (idx < NSf) (&sflag2[0][0][0])[idx] = 0;
    if (idx == 0) g_task_ctr = 0u;
}

// ============================================================================
// Persistent-block wavefront with dynamic work stealing (R11, proven).
// Topological task order along diagonals d = c + l; FC on diagonal c+3.
// ============================================================================
__global__ void __launch_bounds__(128, 4) mega(
    const float* __restrict__ x,
    const float* __restrict__ Wih0, const float* __restrict__ Whh0,
    const float* __restrict__ bih0, const float* __restrict__ bhh0,
    const float* __restrict__ Wih,  const float* __restrict__ Whh,
    const float* __restrict__ bih,  const float* __restrict__ bhh,
    const float* __restrict__ Wfc,  const float* __restrict__ bfc,
    float* __restrict__ out)
{
    __shared__ SmemU sm;
    __shared__ unsigned s_task;
    const int tid = threadIdx.x;

    #pragma unroll 1
    for (;;) {
        __syncthreads();   // previous task fully done (smem reuse)
        if (tid == 0) s_task = atomicAdd(&g_task_ctr, 1u);
        __syncthreads();
        const unsigned k = s_task;
        if (k >= TOTAL_TASKS) break;

        // ---- decode task k -> (kind, l, c, idx) along diagonals
        int kind = -1, l = 0, c = 0, idx = 0;
        {
            int base = 0;
            #pragma unroll 1
            for (int d = 0; d <= 10 && kind < 0; d++) {
                int lmin = (d > 7) ? d - 7 : 0;
                int lmax = (d < 3) ? d : 3;
                int pairs = lmax - lmin + 1;
                int cnt = pairs * (NG + NS) + ((d >= 3) ? NG : 0);
                if ((int)k < base + cnt) {
                    int rem = (int)k - base;
                    #pragma unroll 1
                    for (int ll = lmin; ll <= lmax && kind < 0; ll++) {
                        if (rem < NG) { kind = 0; l = ll; c = d - ll; idx = rem; break; }
                        rem -= NG;
                        if (rem < NS) { kind = 1; l = ll; c = d - ll; idx = rem; break; }
                        rem -= NS;
                    }
                    if (kind < 0) { kind = 2; c = d - 3; idx = rem; }
                }
                base += cnt;
            }
        }
        const int t0 = c * CT;

        if (kind == 0 || kind == 2) {
            // ================= GEMM / FC: one 128-row tile (batch row idx) ======
            const int b = idx;
            if (tid == 0) {
                if (kind == 2)  { while (ld_acq(&sflag2[3][c][b>>1])   == 0) __nanosleep(128); __threadfence(); }
                else if (l > 0) { while (ld_acq(&sflag2[l-1][c][b>>1]) == 0) __nanosleep(128); __threadfence(); }
            }
            __syncthreads();

            const float* X; const float* W; const float* b1; const float* b2;
            float* Out; int K;
            if (kind == 2) {
                X = &g_hout[3][0]; W = Wfc; b1 = bfc; b2 = nullptr; Out = out; K = 64;
            } else if (l == 0) {
                X = x; W = Wih0; b1 = bih0; b2 = bhh0; Out = &g_pre[0][0]; K = 52;
            } else {
                X = &g_hout[l-1][0]; W = Wih + (l-1)*4096;
                b1 = bih + (l-1)*64;  b2 = bhh + (l-1)*64;
                Out = &g_pre[l][0]; K = 64;
            }
            gemm_body(sm.g, X, W, b1, b2, Out, K, (long)b * TLEN + t0);

            if (kind == 0) {
                __threadfence();
                __syncthreads();
                if (tid == 0) st_rel(&gflag[l][c][b], 1);
            }
            continue;
        }

        // ================= SCAN: 2 independent row-engines (named barriers) =====
        const int g = idx;
        const float* Whh_l = (l == 0) ? Whh0 : Whh + (l-1)*4096;
        float* pre  = &g_pre [l][0];
        float* hout = &g_hout[l][0];
        float* hst  = &g_hst [l][0];

        const int r    = tid >> 6;            // row engine (0/1)
        const int u    = tid & 63;
        const int W32  = u >> 5;              // warp-half: outputs [32W, 32W+32)
        const int lane = tid & 31;
        const int og   = lane & 7;            // output group of 4
        const int ks   = lane >> 3;           // k-quarter
        const int K0   = 16 * ks;
        const int jo   = 32*W32 + 4*og + ks;  // output this lane finalizes
        const long b   = 2L*g + r;
        const int bar  = 1 + r;

        if (u == 0) {
            while (ld_acq(&gflag[l][c][b]) == 0) __nanosleep(128);
            if (c > 0) while (ld_acq(&sflag2[l][c-1][g]) == 0) __nanosleep(128);
            __threadfence();
        }
        bar_sync(bar);

        float h0v = (c == 0) ? 0.f : __ldcg(&hst[b*64 + u]);
        sm.s.hbuf[r][0][u] = h0v;
        sm.s.hbuf[r][1][u] = h0v;

        u64 w2[4][8];
        #pragma unroll
        for (int o = 0; o < 4; o++) {
            const float4* wr = reinterpret_cast<const float4*>(Whh_l + (32*W32 + 4*og + o)*64 + K0);
            #pragma unroll
            for (int q = 0; q < 4; q++) {
                float4 w = __ldg(&wr[q]);
                w2[o][2*q]   = pk2(w.x, w.y);
                w2[o][2*q+1] = pk2(w.z, w.w);
            }
        }

        const float* prow = pre  + (b * TLEN + t0) * 64 + jo;
        float*       orow = hout + (b * TLEN + t0) * 64 + jo;

        float pb[8];
        #pragma unroll
        for (int q = 0; q < 8; q++) pb[q] = __ldg(&prow[q * 64]);
        bar_sync(bar);

        #pragma unroll 8
        for (int t = 0; t < CT; t++) {
            float cur = pb[t & 7];
            if (t + 8 < CT) pb[t & 7] = __ldg(&prow[(long)(t + 8) * 64]);

            const ulonglong2* H2 = reinterpret_cast<const ulonglong2*>(&sm.s.hbuf[r][t & 1][K0]);
            ulonglong2 hA = H2[0];
            ulonglong2 hB = H2[1];
            ulonglong2 hC = H2[2];
            ulonglong2 hD = H2[3];

            float P[4];
            #pragma unroll
            for (int o = 0; o < 4; o++) {
                u64 a0 = 0ull, a1 = 0ull;
                FMA2(a0, hA.x, w2[o][0], a0);
                FMA2(a1, hA.y, w2[o][1], a1);
                FMA2(a0, hB.x, w2[o][2], a0);
                FMA2(a1, hB.y, w2[o][3], a1);
                FMA2(a0, hC.x, w2[o][4], a0);
                FMA2(a1, hC.y, w2[o][5], a1);
                FMA2(a0, hD.x, w2[o][6], a0);
                FMA2(a1, hD.y, w2[o][7], a1);
                ADD2(a0, a0, a1);
                float lo, hi; upk2(a0, lo, hi);
                P[o] = lo + hi;
            }
            #pragma unroll
            for (int o = 0; o < 4; o++) {
                P[o] += __shfl_xor_sync(0xffffffffu, P[o], 8);
                P[o] += __shfl_xor_sync(0xffffffffu, P[o], 16);
            }
            float sum = (ks == 0) ? P[0] : (ks == 1) ? P[1] : (ks == 2) ? P[2] : P[3];
            float h = tanh_fast(cur + sum);

            orow[(long)t * 64] = h;
            sm.s.hbuf[r][(t & 1) ^ 1][jo] = h;
            bar_sync(bar);
        }

        hst[b*64 + jo] = sm.s.hbuf[r][0][jo];   // CT even -> final h in phase 0

        __threadfence();
        __syncthreads();                        // join both engines
        if (tid == 0) st_rel(&sflag2[l][c][g], 1);
    }
}

extern "C" void kernel_launch(void* const* d_in, const int* in_sizes, int n_in,
                              void* d_out, int out_size)
{
    const float* x    = (const float*)d_in[0];
    const float* Wih0 = (const float*)d_in[1];
    const float* Whh0 = (const float*)d_in[2];
    const float* bih0 = (const float*)d_in[3];
    const float* bhh0 = (const float*)d_in[4];
    const float* Wih  = (const float*)d_in[5];
    const float* Whh  = (const float*)d_in[6];
    const float* bih  = (const float*)d_in[7];
    const float* bhh  = (const float*)d_in[8];
    const float* Wfc  = (const float*)d_in[9];
    const float* bfc  = (const float*)d_in[10];
    float* out = (float*)d_out;

    zero_flags<<<(4*CHUNKS*BATCH + 255)/256, 256>>>();
    mega<<<NBLK, 128>>>(x, Wih0, Whh0, bih0, bhh0,
                        Wih, Whh, bih, bhh, Wfc, bfc, out);
}

// round 13
// speedup vs baseline: 1.0889x; 1.0889x over previous
#include <cuda_runtime.h>
#include <math.h>

typedef unsigned long long u64;

#define BATCH  512
#define TLEN   1024
#define HID    64
#define M_TOTAL (BATCH*TLEN)
#define CHUNKS 8
#define CT     (TLEN/CHUNKS)          // 128 steps per chunk

#define NBLK        592               // 4 blocks/SM x 148 SMs: all resident
#define NG          512               // gemm tasks per (l,c)  (1 batch row each)
#define NS          256               // scan tasks per (l,c)  (2 batch rows each)
#define TOTAL_TASKS (32*(NG+NS) + CHUNKS*NG)   // 28672

// Per-layer scratch.
__device__ __align__(16) float g_pre [4][M_TOTAL*HID];
__device__ __align__(16) float g_hout[4][M_TOTAL*HID];
__device__ __align__(16) float g_hst [4][BATCH*HID];    // h carry between chunks

// Dependency flags + dynamic task ticket.
__device__ int gflag [4][CHUNKS][BATCH];   // pre(l,c,row) ready
__device__ int sflag2[4][CHUNKS][NS];      // h(l,c, 2-row group) ready
__device__ unsigned g_task_ctr;

__device__ __forceinline__ int ld_acq(const int* p) {
    int v;
    asm volatile("ld.acquire.gpu.global.b32 %0, [%1];" : "=r"(v) : "l"(p) : "memory");
    return v;
}
__device__ __forceinline__ void st_rel(int* p, int v) {
    asm volatile("st.release.gpu.global.b32 [%0], %1;" :: "l"(p), "r"(v) : "memory");
}
__device__ __forceinline__ void bar_sync(int id) {
    asm volatile("bar.sync %0, 64;" :: "r"(id) : "memory");
}

__device__ __forceinline__ u64 pk2(float x, float y) {
    u64 r; asm("mov.b64 %0,{%1,%2};" : "=l"(r) : "f"(x), "f"(y)); return r;
}
__device__ __forceinline__ void upk2(u64 v, float &x, float &y) {
    asm("mov.b64 {%0,%1},%2;" : "=f"(x), "=f"(y) : "l"(v));
}
#define FMA2(d,a,b,c) asm("fma.rn.f32x2 %0,%1,%2,%3;" : "=l"(d) : "l"(a), "l"(b), "l"(c))
#define ADD2(d,a,b)   asm("add.rn.f32x2 %0,%1,%2;"    : "=l"(d) : "l"(a), "l"(b))

__device__ __forceinline__ float tanh_fast(float x) {
    float xc = fminf(fmaxf(x, -15.0f), 15.0f);
    float e;
    asm("ex2.approx.f32 %0, %1;" : "=f"(e) : "f"(xc * 2.885390081777927f));
    float r;
    asm("rcp.approx.f32 %0, %1;" : "=f"(r) : "f"(e + 1.0f));
    return (e - 1.0f) * r;
}

// Shared memory union: gemm staging vs scan h buffers.
struct SmemGemm {
    u64 Xd[32*128];   // 32 KB: k-major dup {x,x}: Xd[kk][m ^ ((kk&15)<<1)]
    u64 Wp[32*32];    // 8 KB:  Wp[kk][np ^ ((kk&7)<<2)] = {W[2np][k],W[2np+1][k]}
};
struct SmemScan {
    float hbuf[2][2][64];   // [row][phase][col]
};
union SmemU {
    SmemGemm g;
    SmemScan s;
};

// ============================================================================
// GEMM tile body, k-major-X variant: 128 threads, 128 rows x 64 cols,
// 8x8 per thread, K staged in two 32-k halves.
// X stored k-major + duplicated with even-xor swizzle so one LDS.128 returns
// two adjacent rows' {x,x} pairs and a warp's 4 row-groups sit in a 256B
// window (2 wavefronts/instr). Per k per warp: 4 X-LDS.128 + 2 W-LDS.128
// (12 wf) vs 64 FMA-pipe cycles -> FMA-bound. Transient regs ~12 -> no spill.
// ============================================================================
__device__ __forceinline__ void gemm_body(
    SmemGemm& sm,
    const float* __restrict__ X, const float* __restrict__ W,
    const float* __restrict__ b1, const float* __restrict__ b2,
    float* __restrict__ Out, int K, long m0)
{
    u64* Xd = sm.Xd;
    u64* Wp = sm.Wp;

    const int tid = threadIdx.x;
    const int nt  = tid & 7;
    const int mt  = tid >> 3;
    const int np0 = nt * 4;
    const int mr  = mt * 8;

    u64 acc[8][4];
    {
        u64 bias[4];
        #pragma unroll
        for (int p = 0; p < 4; p++) {
            int n = (np0 + p) * 2;
            float v0 = b1[n], v1 = b1[n+1];
            if (b2) { v0 += b2[n]; v1 += b2[n+1]; }
            bias[p] = pk2(v0, v1);
        }
        #pragma unroll
        for (int i = 0; i < 8; i++)
            #pragma unroll
            for (int p = 0; p < 4; p++) acc[i][p] = bias[p];
    }

    #pragma unroll
    for (int kh = 0; kh < 2; kh++) {
        const int kbase = kh * 32;
        __syncthreads();   // protect smem reuse across halves

        // ---- stage X half, k-major dup: global read coalesced in k.
        // idx: kk = idx&31, m = idx>>5 (lanes share m, k spans warp).
        #pragma unroll 8
        for (int i = 0; i < 32; i++) {
            int idx = i * 128 + tid;          // 0..4095
            int kk = idx & 31;
            int m  = idx >> 5;
            int k  = kbase + kk;
            float v = (k < K) ? X[(m0 + m) * (long)K + k] : 0.f;
            Xd[kk * 128 + (m ^ ((kk & 15) << 1))] = pk2(v, v);   // 2-way STS max
        }
        // ---- stage W half: Wp[kk][np'] pairs, swizzled
        #pragma unroll
        for (int i = 0; i < 8; i++) {
            int idx = i * 128 + tid;          // 0..1023
            int np = idx >> 5;
            int kk = idx & 31;
            int k  = kbase + kk;
            float w0 = 0.f, w1 = 0.f;
            if (k < K) {
                w0 = W[(2*np)   * (long)K + k];
                w1 = W[(2*np+1) * (long)K + k];
            }
            Wp[kk * 32 + (np ^ ((kk & 7) << 2))] = pk2(w0, w1);
        }
        __syncthreads();

        // ---- compute half
        #pragma unroll 8
        for (int kk = 0; kk < 32; kk++) {
            const int cx = (kk & 15) << 1;    // even xor -> pair-preserving
            int wb = kk * 32 + (np0 ^ ((kk & 7) << 2));
            ulonglong2 wA = *reinterpret_cast<const ulonglong2*>(&Wp[wb]);
            ulonglong2 wB = *reinterpret_cast<const ulonglong2*>(&Wp[wb + 2]);
            const ulonglong2* Xrow = reinterpret_cast<const ulonglong2*>(&Xd[kk * 128]);
            #pragma unroll
            for (int j = 0; j < 4; j++) {
                // one LDS.128: {x,x} pairs for rows mr+2j and mr+2j+1
                ulonglong2 xp = Xrow[((mr + 2*j) ^ cx) >> 1];
                FMA2(acc[2*j  ][0], xp.x, wA.x, acc[2*j  ][0]);
                FMA2(acc[2*j  ][1], xp.x, wA.y, acc[2*j  ][1]);
                FMA2(acc[2*j  ][2], xp.x, wB.x, acc[2*j  ][2]);
                FMA2(acc[2*j  ][3], xp.x, wB.y, acc[2*j  ][3]);
                FMA2(acc[2*j+1][0], xp.y, wA.x, acc[2*j+1][0]);
                FMA2(acc[2*j+1][1], xp.y, wA.y, acc[2*j+1][1]);
                FMA2(acc[2*j+1][2], xp.y, wB.x, acc[2*j+1][2]);
                FMA2(acc[2*j+1][3], xp.y, wB.y, acc[2*j+1][3]);
            }
        }
    }

    const int n0 = np0 * 2;
    #pragma unroll
    for (int i = 0; i < 8; i++) {
        float* dst = &Out[(m0 + mr + i) * 64 + n0];
        ulonglong2 v0, v1;
        v0.x = acc[i][0]; v0.y = acc[i][1];
        v1.x = acc[i][2]; v1.y = acc[i][3];
        *reinterpret_cast<ulonglong2*>(dst)     = v0;
        *reinterpret_cast<ulonglong2*>(dst + 4) = v1;
    }
}

__global__ void zero_flags()
{
    int idx = blockIdx.x * blockDim.x + threadIdx.x;
    const int NGf = 4 * CHUNKS * BATCH;
    const int NSf = 4 * CHUNKS * NS;
    if (idx < NGf) (&gflag [0][0][0])[idx] = 0;
    if (idx < NSf) (&sflag2[0][0][0])[idx] = 0;
    if (idx == 0) g_task_ctr = 0u;
}

// ============================================================================
// Persistent-block wavefront with dynamic work stealing (R11, proven).
// Topological task order along diagonals d = c + l; FC on diagonal c+3.
// ============================================================================
__global__ void __launch_bounds__(128, 4) mega(
    const float* __restrict__ x,
    const float* __restrict__ Wih0, const float* __restrict__ Whh0,
    const float* __restrict__ bih0, const float* __restrict__ bhh0,
    const float* __restrict__ Wih,  const float* __restrict__ Whh,
    const float* __restrict__ bih,  const float* __restrict__ bhh,
    const float* __restrict__ Wfc,  const float* __restrict__ bfc,
    float* __restrict__ out)
{
    __shared__ SmemU sm;
    __shared__ unsigned s_task;
    const int tid = threadIdx.x;

    #pragma unroll 1
    for (;;) {
        __syncthreads();   // previous task fully done (smem reuse)
        if (tid == 0) s_task = atomicAdd(&g_task_ctr, 1u);
        __syncthreads();
        const unsigned k = s_task;
        if (k >= TOTAL_TASKS) break;

        // ---- decode task k -> (kind, l, c, idx) along diagonals
        int kind = -1, l = 0, c = 0, idx = 0;
        {
            int base = 0;
            #pragma unroll 1
            for (int d = 0; d <= 10 && kind < 0; d++) {
                int lmin = (d > 7) ? d - 7 : 0;
                int lmax = (d < 3) ? d : 3;
                int pairs = lmax - lmin + 1;
                int cnt = pairs * (NG + NS) + ((d >= 3) ? NG : 0);
                if ((int)k < base + cnt) {
                    int rem = (int)k - base;
                    #pragma unroll 1
                    for (int ll = lmin; ll <= lmax && kind < 0; ll++) {
                        if (rem < NG) { kind = 0; l = ll; c = d - ll; idx = rem; break; }
                        rem -= NG;
                        if (rem < NS) { kind = 1; l = ll; c = d - ll; idx = rem; break; }
                        rem -= NS;
                    }
                    if (kind < 0) { kind = 2; c = d - 3; idx = rem; }
                }
                base += cnt;
            }
        }
        const int t0 = c * CT;

        if (kind == 0 || kind == 2) {
            // ================= GEMM / FC: one 128-row tile (batch row idx) ======
            const int b = idx;
            if (tid == 0) {
                if (kind == 2)  { while (ld_acq(&sflag2[3][c][b>>1])   == 0) __nanosleep(128); __threadfence(); }
                else if (l > 0) { while (ld_acq(&sflag2[l-1][c][b>>1]) == 0) __nanosleep(128); __threadfence(); }
            }
            __syncthreads();

            const float* X; const float* W; const float* b1; const float* b2;
            float* Out; int K;
            if (kind == 2) {
                X = &g_hout[3][0]; W = Wfc; b1 = bfc; b2 = nullptr; Out = out; K = 64;
            } else if (l == 0) {
                X = x; W = Wih0; b1 = bih0; b2 = bhh0; Out = &g_pre[0][0]; K = 52;
            } else {
                X = &g_hout[l-1][0]; W = Wih + (l-1)*4096;
                b1 = bih + (l-1)*64;  b2 = bhh + (l-1)*64;
                Out = &g_pre[l][0]; K = 64;
            }
            gemm_body(sm.g, X, W, b1, b2, Out, K, (long)b * TLEN + t0);

            if (kind == 0) {
                __threadfence();
                __syncthreads();
                if (tid == 0) st_rel(&gflag[l][c][b], 1);
            }
            continue;
        }

        // ================= SCAN: 2 independent row-engines (named barriers) =====
        const int g = idx;
        const float* Whh_l = (l == 0) ? Whh0 : Whh + (l-1)*4096;
        float* pre  = &g_pre [l][0];
        float* hout = &g_hout[l][0];
        float* hst  = &g_hst [l][0];

        const int r    = tid >> 6;            // row engine (0/1)
        const int u    = tid & 63;
        const int W32  = u >> 5;              // warp-half: outputs [32W, 32W+32)
        const int lane = tid & 31;
        const int og   = lane & 7;            // output group of 4
        const int ks   = lane >> 3;           // k-quarter
        const int K0   = 16 * ks;
        const int jo   = 32*W32 + 4*og + ks;  // output this lane finalizes
        const long b   = 2L*g + r;
        const int bar  = 1 + r;

        if (u == 0) {
            while (ld_acq(&gflag[l][c][b]) == 0) __nanosleep(128);
            if (c > 0) while (ld_acq(&sflag2[l][c-1][g]) == 0) __nanosleep(128);
            __threadfence();
        }
        bar_sync(bar);

        float h0v = (c == 0) ? 0.f : __ldcg(&hst[b*64 + u]);
        sm.s.hbuf[r][0][u] = h0v;
        sm.s.hbuf[r][1][u] = h0v;

        u64 w2[4][8];
        #pragma unroll
        for (int o = 0; o < 4; o++) {
            const float4* wr = reinterpret_cast<const float4*>(Whh_l + (32*W32 + 4*og + o)*64 + K0);
            #pragma unroll
            for (int q = 0; q < 4; q++) {
                float4 w = __ldg(&wr[q]);
                w2[o][2*q]   = pk2(w.x, w.y);
                w2[o][2*q+1] = pk2(w.z, w.w);
            }
        }

        const float* prow = pre  + (b * TLEN + t0) * 64 + jo;
        float*       orow = hout + (b * TLEN + t0) * 64 + jo;

        float pb[8];
        #pragma unroll
        for (int q = 0; q < 8; q++) pb[q] = __ldg(&prow[q * 64]);
        bar_sync(bar);

        #pragma unroll 8
        for (int t = 0; t < CT; t++) {
            float cur = pb[t & 7];
            if (t + 8 < CT) pb[t & 7] = __ldg(&prow[(long)(t + 8) * 64]);

            const ulonglong2* H2 = reinterpret_cast<const ulonglong2*>(&sm.s.hbuf[r][t & 1][K0]);
            ulonglong2 hA = H2[0];
            ulonglong2 hB = H2[1];
            ulonglong2 hC = H2[2];
            ulonglong2 hD = H2[3];

            float P[4];
            #pragma unroll
            for (int o = 0; o < 4; o++) {
                u64 a0 = 0ull, a1 = 0ull;
                FMA2(a0, hA.x, w2[o][0], a0);
                FMA2(a1, hA.y, w2[o][1], a1);
                FMA2(a0, hB.x, w2[o][2], a0);
                FMA2(a1, hB.y, w2[o][3], a1);
                FMA2(a0, hC.x, w2[o][4], a0);
                FMA2(a1, hC.y, w2[o][5], a1);
                FMA2(a0, hD.x, w2[o][6], a0);
                FMA2(a1, hD.y, w2[o][7], a1);
                ADD2(a0, a0, a1);
                float lo, hi; upk2(a0, lo, hi);
                P[o] = lo + hi;
            }
            #pragma unroll
            for (int o = 0; o < 4; o++) {
                P[o] += __shfl_xor_sync(0xffffffffu, P[o], 8);
                P[o] += __shfl_xor_sync(0xffffffffu, P[o], 16);
            }
            float sum = (ks == 0) ? P[0] : (ks == 1) ? P[1] : (ks == 2) ? P[2] : P[3];
            float h = tanh_fast(cur + sum);

            orow[(long)t * 64] = h;
            sm.s.hbuf[r][(t & 1) ^ 1][jo] = h;
            bar_sync(bar);
        }

        hst[b*64 + jo] = sm.s.hbuf[r][0][jo];   // CT even -> final h in phase 0

        __threadfence();
        __syncthreads();                        // join both engines
        if (tid == 0) st_rel(&sflag2[l][c][g], 1);
    }
}

extern "C" void kernel_launch(void* const* d_in, const int* in_sizes, int n_in,
                              void* d_out, int out_size)
{
    const float* x    = (const float*)d_in[0];
    const float* Wih0 = (const float*)d_in[1];
    const float* Whh0 = (const float*)d_in[2];
    const float* bih0 = (const float*)d_in[3];
    const float* bhh0 = (const float*)d_in[4];
    const float* Wih  = (const float*)d_in[5];
    const float* Whh  = (const float*)d_in[6];
    const float* bih  = (const float*)d_in[7];
    const float* bhh  = (const float*)d_in[8];
    const float* Wfc  = (const float*)d_in[9];
    const float* bfc  = (const float*)d_in[10];
    float* out = (float*)d_out;

    zero_flags<<<(4*CHUNKS*BATCH + 255)/256, 256>>>();
    mega<<<NBLK, 128>>>(x, Wih0, Whh0, bih0, bhh0,
                        Wih, Whh, bih, bhh, Wfc, bfc, out);
}